// round 10
// baseline (speedup 1.0000x reference)
#include <cuda_runtime.h>
#include <math.h>

#define BB 16      // batch
#define TT 1024    // sequence
#define JJ 128     // input dim
#define HH 64      // hidden (complex) dim

// Per-(b, segment) ZERO-STATE carry C (complex, 64 h).
__device__ __align__(16) float2 g_C[BB * 8 * HH];
// lam^k table, k = 1..128:  g_L[(k-1)*64 + h]
__device__ __align__(16) float2 g_L[128 * HH];
// Incoming segment state S per (b, seg, h).
__device__ __align__(16) float2 g_S[BB * 8 * HH];

// ---------------------------------------------------------------------------
// tf32 helpers
// ---------------------------------------------------------------------------
__device__ __forceinline__ unsigned tf32bits(float v) {
    unsigned r;
    asm("cvt.rna.tf32.f32 %0, %1;" : "=r"(r) : "f"(v));
    return r;
}
__device__ __forceinline__ void mma_tf32(float& d0, float& d1, float& d2, float& d3,
                                         unsigned a0, unsigned a1, unsigned a2, unsigned a3,
                                         unsigned b0, unsigned b1) {
    asm("mma.sync.aligned.m16n8k8.row.col.f32.tf32.tf32.f32 "
        "{%0,%1,%2,%3}, {%4,%5,%6,%7}, {%8,%9}, {%0,%1,%2,%3};"
        : "+f"(d0), "+f"(d1), "+f"(d2), "+f"(d3)
        : "r"(a0), "r"(a1), "r"(a2), "r"(a3), "r"(b0), "r"(b1));
}

// Split 8 consecutive j (two float4) into tf32 hi/lo and store pair-permuted:
// positions {e,e+4} adjacent -> fragment (k, k+4) pairs readable as LDS.64.
__device__ __forceinline__ void stage8(float* hi, float* lo,
                                       const float4 v0, const float4 v1) {
    float e[8] = {v0.x, v0.y, v0.z, v0.w, v1.x, v1.y, v1.z, v1.w};
    float hv[8], lv[8];
#pragma unroll
    for (int i = 0; i < 8; ++i) {
        hv[i] = __uint_as_float(tf32bits(e[i]));
        lv[i] = e[i] - hv[i];
    }
    *reinterpret_cast<float4*>(hi)     = make_float4(hv[0], hv[4], hv[1], hv[5]);
    *reinterpret_cast<float4*>(hi + 4) = make_float4(hv[2], hv[6], hv[3], hv[7]);
    *reinterpret_cast<float4*>(lo)     = make_float4(lv[0], lv[4], lv[1], lv[5]);
    *reinterpret_cast<float4*>(lo + 4) = make_float4(lv[2], lv[6], lv[3], lv[7]);
}

// ---------------------------------------------------------------------------
// K1: fused GEMM (3xTF32) + zero-state segment scan.
// Grid 128 = 16 b x 8 t-segs (128 t). 512 threads = 16 warps (4/SMSP).
// Warp grid 4(t) x 4(h); warp tile 32t x 16h = 2m x 2n m16n8k8 tiles.
// Staging: pair-permuted, XOR-swizzled rows (stride 64, conflict-free
// LDS.64 fragment loads). K=128 in 2 chunks of 64.
// Scan: thread = (4h quad, 4t chunk); float4 loads/stores throughout.
// ---------------------------------------------------------------------------
// smem floats: xhi[0,8192) xlo[8192,16384) bhi[16384,20480) blo[20480,24576)
// aliased after mainloop: sD[0,8704) V/W[8704,16896)
#define K1_SMEM_BYTES (24576 * 4)

__global__ __launch_bounds__(512) void fused_kernel(const float* __restrict__ x,
                                                    const float* __restrict__ Bm,
                                                    const float* __restrict__ nu,
                                                    const float* __restrict__ theta,
                                                    float* __restrict__ out) {
    extern __shared__ __align__(16) float sm[];
    float* xhi = sm;
    float* xlo = sm + 8192;
    float* bhi = sm + 16384;
    float* blo = sm + 20480;

    const int tid  = threadIdx.x;
    const int lane = tid & 31;
    const int wid  = tid >> 5;
    const int wt   = wid >> 2;          // 0..3 -> 32 t
    const int wh   = wid & 3;           // 0..3 -> 16 h
    const int b    = blockIdx.x >> 3;
    const int ts   = blockIdx.x & 7;
    const int t0   = ts * 128;
    const int lr   = lane >> 2;         // 0..7
    const int lc   = lane & 3;          // 0..3

    float acc[2][2][4];
#pragma unroll
    for (int m = 0; m < 2; ++m)
#pragma unroll
        for (int n = 0; n < 2; ++n)
#pragma unroll
            for (int q = 0; q < 4; ++q) acc[m][n][q] = 0.f;

    const float4* x4 = reinterpret_cast<const float4*>(x);
    const float4* B4 = reinterpret_cast<const float4*>(Bm);

    for (int kc = 0; kc < 2; ++kc) {
        if (kc) __syncthreads();
        // Stage x: 128 t x 8 blocks of 8 j -> 1024 items, 2 per thread.
#pragma unroll
        for (int i = 0; i < 2; ++i) {
            int item = tid + 512 * i;
            int t  = item >> 3;
            int cb = item & 7;
            int gidx = (b * TT + t0 + t) * 32 + kc * 16 + cb * 2;
            float4 v0 = x4[gidx];
            float4 v1 = x4[gidx + 1];
            int off = t * 64 + ((cb ^ (t & 7)) * 8);
            stage8(xhi + off, xlo + off, v0, v1);
        }
        // Stage B: 64 h x 8 blocks -> 512 items, 1 per thread.
        {
            int h  = tid >> 3;
            int cb = tid & 7;
            int gidx = h * 32 + kc * 16 + cb * 2;
            float4 v0 = B4[gidx];
            float4 v1 = B4[gidx + 1];
            int off = h * 64 + ((cb ^ (h & 7)) * 8);
            stage8(bhi + off, blo + off, v0, v1);
        }
        __syncthreads();

#pragma unroll
        for (int ks = 0; ks < 8; ++ks) {
            const int co = ((ks ^ lr) * 8) + lc * 2;   // swizzled column offset
            uint2 axh[2][2], axl[2][2];
#pragma unroll
            for (int m = 0; m < 2; ++m) {
                int r0 = (wt * 32 + m * 16 + lr) * 64 + co;
                axh[m][0] = *reinterpret_cast<const uint2*>(xhi + r0);
                axh[m][1] = *reinterpret_cast<const uint2*>(xhi + r0 + 8 * 64);
                axl[m][0] = *reinterpret_cast<const uint2*>(xlo + r0);
                axl[m][1] = *reinterpret_cast<const uint2*>(xlo + r0 + 8 * 64);
            }
            uint2 bh[2], bl[2];
#pragma unroll
            for (int n = 0; n < 2; ++n) {
                int rn = (wh * 16 + n * 8 + lr) * 64 + co;
                bh[n] = *reinterpret_cast<const uint2*>(bhi + rn);
                bl[n] = *reinterpret_cast<const uint2*>(blo + rn);
            }
#pragma unroll
            for (int m = 0; m < 2; ++m)
#pragma unroll
                for (int n = 0; n < 2; ++n) {
                    mma_tf32(acc[m][n][0], acc[m][n][1], acc[m][n][2], acc[m][n][3],
                             axh[m][0].x, axh[m][1].x, axh[m][0].y, axh[m][1].y,
                             bh[n].x, bh[n].y);
                    mma_tf32(acc[m][n][0], acc[m][n][1], acc[m][n][2], acc[m][n][3],
                             axh[m][0].x, axh[m][1].x, axh[m][0].y, axh[m][1].y,
                             bl[n].x, bl[n].y);
                    mma_tf32(acc[m][n][0], acc[m][n][1], acc[m][n][2], acc[m][n][3],
                             axl[m][0].x, axl[m][1].x, axl[m][0].y, axl[m][1].y,
                             bh[n].x, bh[n].y);
                }
        }
    }
    __syncthreads();

    // Stage D = Bx into smem as [t][h], stride 68 (aliases staging region).
    float* sD   = sm;                       // 128 * 68 floats
    float* Vr_s = sm + 8704;                // 32 * 64
    float* Vi_s = sm + 8704 + 2048;
    float* Wr_s = sm + 8704 + 4096;
    float* Wi_s = sm + 8704 + 6144;
#pragma unroll
    for (int m = 0; m < 2; ++m)
#pragma unroll
        for (int n = 0; n < 2; ++n) {
            int tr = wt * 32 + m * 16 + lr;
            int hc = wh * 16 + n * 8 + 2 * lc;
            sD[tr * 68 + hc]           = acc[m][n][0];
            sD[tr * 68 + hc + 1]       = acc[m][n][1];
            sD[(tr + 8) * 68 + hc]     = acc[m][n][2];
            sD[(tr + 8) * 68 + hc + 1] = acc[m][n][3];
        }
    __syncthreads();

    // ---- Segment-local scan: thread = (hq 0..15, chunk 0..31 of 4 t) ----
    const int hq = tid & 15;
    const int ch = tid >> 4;
    const int h0 = hq * 4;

    float Lr[4], Li[4];
#pragma unroll
    for (int q = 0; q < 4; ++q) {
        int hh = h0 + q;
        float m = expf(-expf(nu[hh]));
        float s, c;
        sincosf(theta[hh], &s, &c);
        Lr[q] = m * c;
        Li[q] = m * s;
    }

    float4 u[4];
#pragma unroll
    for (int k = 0; k < 4; ++k)
        u[k] = *reinterpret_cast<const float4*>(&sD[(ch * 4 + k) * 68 + h0]);

    // Phase A: 4-step local scan from zero -> chunk value V (4 h chains)
    float yr[4] = {0.f, 0.f, 0.f, 0.f}, yi[4] = {0.f, 0.f, 0.f, 0.f};
#pragma unroll
    for (int k = 0; k < 4; ++k) {
        float uu[4] = {u[k].x, u[k].y, u[k].z, u[k].w};
#pragma unroll
        for (int q = 0; q < 4; ++q) {
            float nyr = fmaf(Lr[q], yr[q], fmaf(-Li[q], yi[q], uu[q]));
            float nyi = fmaf(Lr[q], yi[q], Li[q] * yr[q]);
            yr[q] = nyr; yi[q] = nyi;
        }
    }
#pragma unroll
    for (int q = 0; q < 4; ++q) {
        Vr_s[ch * 64 + h0 + q] = yr[q];
        Vi_s[ch * 64 + h0 + q] = yi[q];
    }
    __syncthreads();

    // Combine (tid<64): serial prefix over 32 chunks; P = lam^4.
    if (tid < 64) {
        const int h = tid;
        float m = expf(-expf(nu[h]));
        float s, c;
        sincosf(theta[h], &s, &c);
        float lr2 = m * c, li2 = m * s;
        float Pr = lr2, Pi = li2;
#pragma unroll
        for (int sq = 0; sq < 2; ++sq) {
            float nr = Pr * Pr - Pi * Pi;
            float ni = 2.f * Pr * Pi;
            Pr = nr; Pi = ni;
        }
        float wr = 0.f, wi = 0.f;
        Wr_s[h] = 0.f; Wi_s[h] = 0.f;
#pragma unroll 4
        for (int cc = 1; cc < 32; ++cc) {
            float vr = Vr_s[(cc - 1) * 64 + h];
            float vi = Vi_s[(cc - 1) * 64 + h];
            float nwr = vr + (Pr * wr - Pi * wi);
            float nwi = vi + (Pr * wi + Pi * wr);
            wr = nwr; wi = nwi;
            Wr_s[cc * 64 + h] = wr;
            Wi_s[cc * 64 + h] = wi;
        }
        float vr = Vr_s[31 * 64 + h];
        float vi = Vi_s[31 * 64 + h];
        float Cr = vr + (Pr * wr - Pi * wi);
        float Ci = vi + (Pr * wi + Pi * wr);
        g_C[(b * 8 + ts) * 64 + h] = make_float2(Cr, Ci);
    }
    __syncthreads();

    // Phase C: rerun with incoming chunk state; float4 stores.
#pragma unroll
    for (int q = 0; q < 4; ++q) {
        yr[q] = Wr_s[ch * 64 + h0 + q];
        yi[q] = Wi_s[ch * 64 + h0 + q];
    }
    float* op = out + (b * TT + t0 + ch * 4) * (2 * HH) + h0;
#pragma unroll
    for (int k = 0; k < 4; ++k) {
        float uu[4] = {u[k].x, u[k].y, u[k].z, u[k].w};
#pragma unroll
        for (int q = 0; q < 4; ++q) {
            float nyr = fmaf(Lr[q], yr[q], fmaf(-Li[q], yi[q], uu[q]));
            float nyi = fmaf(Lr[q], yi[q], Li[q] * yr[q]);
            yr[q] = nyr; yi[q] = nyi;
        }
        *reinterpret_cast<float4*>(op + k * 128) =
            make_float4(yr[0], yr[1], yr[2], yr[3]);
        *reinterpret_cast<float4*>(op + k * 128 + 64) =
            make_float4(yi[0], yi[1], yi[2], yi[3]);
    }
}

// ---------------------------------------------------------------------------
// Prep: lam^k table + incoming states S (one thread per item, ONCE).
// ---------------------------------------------------------------------------
__global__ __launch_bounds__(128) void prep_kernel(const float* __restrict__ nu,
                                                   const float* __restrict__ theta) {
    const int gid = blockIdx.x * 128 + threadIdx.x;   // 0..8191
    const int h   = gid & 63;
    const int kk  = (gid >> 6) + 1;                   // 1..128

    const float enu = expf(nu[h]);
    const float th  = theta[h];

    {
        float m = expf(-(float)kk * enu);
        float s, c;
        sincosf((float)kk * th, &s, &c);
        g_L[(kk - 1) * 64 + h] = make_float2(m * c, m * s);
    }

    const int b   = gid >> 9;
    const int seg = (gid >> 6) & 7;
    float mq = expf(-128.f * enu);
    float sq, cq;
    sincosf(128.f * th, &sq, &cq);
    const float Qr = mq * cq, Qi = mq * sq;
    float Sr = 1.f, Si = 0.f;
    for (int g = 0; g < seg; ++g) {
        float2 cg = g_C[(b * 8 + g) * 64 + h];
        float nr = Qr * Sr - Qi * Si + cg.x;
        float ni = Qr * Si + Qi * Sr + cg.y;
        Sr = nr; Si = ni;
    }
    g_S[(b * 8 + seg) * 64 + h] = make_float2(Sr, Si);
}

// ---------------------------------------------------------------------------
// Fixup: out[b,t,h] += lam_h^(tl+1) * S(b,seg,h).  Chain-free table loads.
// ---------------------------------------------------------------------------
__global__ __launch_bounds__(256) void fixup_kernel(float* __restrict__ out) {
    const int tid = threadIdx.x;
    const int bx  = blockIdx.x;         // 0..255
    const int b   = bx >> 4;
    const int tb  = bx & 15;
    const int tt  = tid >> 4;
    const int hq  = tid & 15;
    const int h0  = hq * 4;
    const int t0  = tb * 64 + tt * 4;
    const int seg = t0 >> 7;

    const float4* Sp = reinterpret_cast<const float4*>(&g_S[(b * 8 + seg) * 64 + h0]);
    float4 s01 = Sp[0], s23 = Sp[1];
    const float Sr[4] = {s01.x, s01.z, s23.x, s23.z};
    const float Si[4] = {s01.y, s01.w, s23.y, s23.w};

#pragma unroll
    for (int i = 0; i < 4; ++i) {
        const int t = t0 + i;
        const int k = (t & 127) + 1;
        const float4* Lp = reinterpret_cast<const float4*>(&g_L[(k - 1) * 64 + h0]);
        float4 l01 = Lp[0], l23 = Lp[1];
        float lkr[4] = {l01.x, l01.z, l23.x, l23.z};
        float lki[4] = {l01.y, l01.w, l23.y, l23.w};

        float* p = out + (b * TT + t) * (2 * HH) + h0;
        float4 re = *reinterpret_cast<float4*>(p);
        float4 im = *reinterpret_cast<float4*>(p + 64);
        re.x += lkr[0] * Sr[0] - lki[0] * Si[0];
        re.y += lkr[1] * Sr[1] - lki[1] * Si[1];
        re.z += lkr[2] * Sr[2] - lki[2] * Si[2];
        re.w += lkr[3] * Sr[3] - lki[3] * Si[3];
        im.x += lkr[0] * Si[0] + lki[0] * Sr[0];
        im.y += lkr[1] * Si[1] + lki[1] * Sr[1];
        im.z += lkr[2] * Si[2] + lki[2] * Sr[2];
        im.w += lkr[3] * Si[3] + lki[3] * Sr[3];
        *reinterpret_cast<float4*>(p)      = re;
        *reinterpret_cast<float4*>(p + 64) = im;
    }
}

// ---------------------------------------------------------------------------
extern "C" void kernel_launch(void* const* d_in, const int* in_sizes, int n_in,
                              void* d_out, int out_size) {
    const float* x     = (const float*)d_in[0];   // [16,1024,128]
    const float* Bm    = (const float*)d_in[1];   // [64,128]
    const float* nu    = (const float*)d_in[2];   // [64]
    const float* theta = (const float*)d_in[3];   // [64]
    float* out = (float*)d_out;                   // [16,1024,128]

    cudaFuncSetAttribute(fused_kernel,
                         cudaFuncAttributeMaxDynamicSharedMemorySize,
                         K1_SMEM_BYTES);
    fused_kernel<<<128, 512, K1_SMEM_BYTES>>>(x, Bm, nu, theta, out);
    prep_kernel<<<64, 128>>>(nu, theta);
    fixup_kernel<<<256, 256>>>(out);
}